// round 12
// baseline (speedup 1.0000x reference)
#include <cuda_runtime.h>

// Problem constants
#define Bn 16
#define Cn 512
#define Hn 80
#define Wn 80
#define HWn (Hn*Wn)          // 6400
#define CHWn (Cn*HWn)        // 3276800
#define NPIX (Bn*HWn)        // 102400

// counting-sort chunks: 64 pixels per block, 16 channel-groups -> 1024 thr/blk
#define CHUNK_PIX 64
#define NGRP 16
#define GRP_C (Cn/NGRP)                 // 32 channels per group
#define TPB_F (CHUNK_PIX*NGRP)          // 1024
#define NCHUNK 100                      // chunks per batch (6400/64)
#define NBLK (Bn*NCHUNK)                // 1600 blocks
#define NCNT (Bn*Cn*NCHUNK)             // 819200 counters, order (b,c,chunk)

// two-level scan of NCNT counters: 800 blocks x 1024 (exact)
#define K3A_BLKS 800
#define K3A_TPB 1024

// ---- scratch (allocation-free: __device__ globals) ----
__device__ unsigned int g_rec[NPIX * 2];   // 2 det slots/pixel: (c<<16)|rank, ~0u=empty
__device__ unsigned int g_cnt[NCNT];       // counts per (b,c,chunk)
__device__ unsigned int g_off[NCNT];       // exclusive within 1024-superblock
__device__ unsigned int g_bsum[K3A_BLKS];
__device__ unsigned int g_bbase[K3A_BLKS];

// ---------------------------------------------------------------------------
// K0: init output padding only
__global__ void k0_init(float4* __restrict__ out4, int n4, int half4) {
    int i = blockIdx.x * blockDim.x + threadIdx.x;
    if (i < half4) {
        out4[i] = make_float4(-1.f, -1.f, -1.f, -1.f);       // grid padding
    } else if (i < n4) {
        out4[i] = make_float4(-4.5f, -4.5f, -4.5f, -4.5f);   // 8*(-1)+3.5
    }
}

// ---------------------------------------------------------------------------
// neighbor test: v (>=0) must be >= all in-bounds raw 3x3 neighbors
// (v >= relu(n) <=> v >= n when v >= 0). Rare path.
__device__ __noinline__ bool neigh_ok(const float* __restrict__ plane,
                                      float v, int h, int w) {
    #pragma unroll
    for (int dh = -1; dh <= 1; dh++) {
        int nh = h + dh;
        if (nh < 0 || nh >= Hn) continue;
        #pragma unroll
        for (int dw = -1; dw <= 1; dw++) {
            if (dh == 0 && dw == 0) continue;
            int nw = w + dw;
            if (nw < 0 || nw >= Wn) continue;
            if (v < plane[nh * Wn + nw]) return false;
        }
    }
    return true;
}

// ---------------------------------------------------------------------------
// Fused: 16 threads per pixel (32 channels each), 64 pixels per block.
// Phase A: per-thread tie-tracking scan (R10/R11-proven accumulator logic).
// Merge:   leader thread per pixel combines 16 group results in ascending
//          group (= channel) order -> two smallest tied channels.
// Phase B: 3x3 local-max confirm per candidate channel (leaders).
// Phase C: counting-sort bookkeeping — proven verbatim.
__global__ void __launch_bounds__(TPB_F) kfused(const float* __restrict__ x) {
    __shared__ unsigned int s_mb[TPB_F];     // group max bits (relu >= 0)
    __shared__ unsigned int s_cand[TPB_F];   // cA | cB<<16 (0xFFFF = empty)
    __shared__ unsigned char s_nd[TPB_F];    // tie count (saturated at 3)
    __shared__ unsigned int bucket[Cn];      // per-channel counts, this chunk
    __shared__ unsigned int ch[CHUNK_PIX];   // packed det channels per pixel

    int blk = blockIdx.x;                    // 1600
    int t = threadIdx.x;
    int pix = t & (CHUNK_PIX - 1);
    int grp = t >> 6;                        // 0..15
    int b     = blk / NCHUNK;
    int chunk = blk - b * NCHUNK;
    int hw = chunk * CHUNK_PIX + pix;
    int cbase = grp * GRP_C;
    const float* base = x + (size_t)b * CHWn + (size_t)cbase * HWn + hw;

    if (t < Cn) bucket[t] = 0u;

    // ---- Phase A: tie-tracking scan of 32 channels (4 accumulators) ----
    float m0 = 0.f, m1 = 0.f, m2 = 0.f, m3 = 0.f;
    int   a0 = -1,  a1 = -1,  a2 = -1,  a3 = -1;     // first tied channel
    int   b0 = -1,  b1 = -1,  b2 = -1,  b3 = -1;     // second tied channel
    int   n0 = 0,   n1 = 0,   n2 = 0,   n3 = 0;      // tie counts
    #pragma unroll
    for (int c = 0; c < GRP_C; c += 4) {
        float v0 = fmaxf(base[(size_t)(c+0) * HWn], 0.f);
        float v1 = fmaxf(base[(size_t)(c+1) * HWn], 0.f);
        float v2 = fmaxf(base[(size_t)(c+2) * HWn], 0.f);
        float v3 = fmaxf(base[(size_t)(c+3) * HWn], 0.f);
        if (v0 > m0)      { m0 = v0; a0 = cbase + c+0; n0 = 1; }
        else if (v0 == m0 && m0 > 0.f) { if (n0 == 1) b0 = cbase + c+0; n0++; }
        if (v1 > m1)      { m1 = v1; a1 = cbase + c+1; n1 = 1; }
        else if (v1 == m1 && m1 > 0.f) { if (n1 == 1) b1 = cbase + c+1; n1++; }
        if (v2 > m2)      { m2 = v2; a2 = cbase + c+2; n2 = 1; }
        else if (v2 == m2 && m2 > 0.f) { if (n2 == 1) b2 = cbase + c+2; n2++; }
        if (v3 > m3)      { m3 = v3; a3 = cbase + c+3; n3 = 1; }
        else if (v3 == m3 && m3 > 0.f) { if (n3 == 1) b3 = cbase + c+3; n3++; }
    }
    float m = fmaxf(fmaxf(m0, m1), fmaxf(m2, m3));

    // per-thread merge: two smallest tied channels within this group (proven)
    int cand[8];
    #pragma unroll
    for (int i = 0; i < 8; i++) cand[i] = 0x7FFFFFFF;
    int ndT = 0;
    if (m > 0.f) {
        if (m0 == m) { cand[0] = a0; if (n0 > 1) cand[1] = b0; ndT += n0; }
        if (m1 == m) { cand[2] = a1; if (n1 > 1) cand[3] = b1; ndT += n1; }
        if (m2 == m) { cand[4] = a2; if (n2 > 1) cand[5] = b2; ndT += n2; }
        if (m3 == m) { cand[6] = a3; if (n3 > 1) cand[7] = b3; ndT += n3; }
    }
    int cA = 0x7FFFFFFF, cB = 0x7FFFFFFF;
    #pragma unroll
    for (int i = 0; i < 8; i++) cA = min(cA, cand[i]);
    #pragma unroll
    for (int i = 0; i < 8; i++) if (cand[i] > cA) cB = min(cB, cand[i]);

    s_mb[t]   = __float_as_uint(m);
    s_cand[t] = (unsigned)(cA & 0xFFFF) | ((unsigned)(cB & 0xFFFF) << 16);
    s_nd[t]   = (unsigned char)min(ndT, 3);
    __syncthreads();

    // ---- leader merge + Phase B + Phase C front half ----
    unsigned int c0 = 0xFFFFu, c1 = 0xFFFFu;
    if (t < CHUNK_PIX) {
        unsigned int mb = 0u;
        #pragma unroll
        for (int g = 0; g < NGRP; g++) mb = max(mb, s_mb[g * CHUNK_PIX + t]);
        // collect candidates in ascending group (= channel) order
        unsigned int tA = 0xFFFFu, tB = 0xFFFFu;
        int ndtot = 0;
        if (mb != 0u) {                         // relu bits: 0 iff m == 0
            #pragma unroll
            for (int g = 0; g < NGRP; g++) {
                int gi = g * CHUNK_PIX + t;
                if (s_mb[gi] == mb) {
                    unsigned int pk = s_cand[gi];
                    unsigned int la = pk & 0xFFFFu, lb = pk >> 16;
                    if (la != 0xFFFFu) { if (tA == 0xFFFFu) tA = la; else if (tB == 0xFFFFu) tB = la; }
                    if (lb != 0xFFFFu) { if (tA == 0xFFFFu) tA = lb; else if (tB == 0xFFFFu) tB = lb; }
                    ndtot += (int)s_nd[gi];
                }
            }
        }
        float mv = __uint_as_float(mb);
        int h = hw / Wn, w = hw - (hw / Wn) * Wn;
        if (ndtot >= 1) {
            bool d0 = neigh_ok(x + (size_t)b * CHWn + (size_t)tA * HWn, mv, h, w);
            bool d1 = (ndtot >= 2) && (tB != 0xFFFFu) &&
                      neigh_ok(x + (size_t)b * CHWn + (size_t)tB * HWn, mv, h, w);
            if (d0) { c0 = tA; if (d1) c1 = tB; }
            else if (d1) { c0 = tB; }
        } else if (mb == 0u) {
            // degenerate pixel (all channels <= 0): prob 2^-512; exact rescan.
            int nd = 0;
            for (int c = 0; c < Cn && nd < 2; c++) {
                const float* plane = x + (size_t)b * CHWn + (size_t)c * HWn;
                if (fmaxf(plane[h * Wn + w], 0.f) == 0.f && neigh_ok(plane, 0.f, h, w)) {
                    if (nd == 0) c0 = (unsigned)c; else c1 = (unsigned)c;
                    nd++;
                }
            }
        }
        if (c0 != 0xFFFFu) atomicAdd(&bucket[c0], 1u);
        if (c1 != 0xFFFFu) atomicAdd(&bucket[c1], 1u);
        ch[t] = c0 | (c1 << 16);
    }
    __syncthreads();

    // ---- Phase C back half: exact pixel-order ranks (proven) ----
    if (t < CHUNK_PIX) {
        unsigned int r0 = 0, r1 = 0;
        if (c0 != 0xFFFFu) {
            for (int q = 0; q < t; q++) {
                unsigned int wv = ch[q];
                unsigned int lo = wv & 0xFFFFu, hi = wv >> 16;
                r0 += (lo == c0) + (hi == c0);
                r1 += (lo == c1) + (hi == c1);
            }
        }
        int p = b * HWn + hw;
        g_rec[2*p + 0] = (c0 != 0xFFFFu) ? ((c0 << 16) | r0) : 0xFFFFFFFFu;
        g_rec[2*p + 1] = (c1 != 0xFFFFu) ? ((c1 << 16) | r1) : 0xFFFFFFFFu;
    }
    if (t < Cn)
        g_cnt[(b * Cn + t) * NCHUNK + chunk] = bucket[t];
}

// ---------------------------------------------------------------------------
// K3a: 800 blocks x 1024 counts (1/thread): local exclusive scan + block sum.
__global__ void __launch_bounds__(K3A_TPB) k3a_scan() {
    int sb = blockIdx.x;
    int t = threadIdx.x;
    int lane = t & 31;
    int warp = t >> 5;
    unsigned int v = g_cnt[sb * K3A_TPB + t];
    unsigned int incl = v;
    #pragma unroll
    for (int off = 1; off < 32; off <<= 1) {
        unsigned int n = __shfl_up_sync(0xFFFFFFFFu, incl, off);
        if (lane >= off) incl += n;
    }
    __shared__ unsigned int ws[32];
    if (lane == 31) ws[warp] = incl;
    __syncthreads();
    if (t < 32) {
        unsigned int w = ws[t];
        unsigned int iw = w;
        #pragma unroll
        for (int off = 1; off < 32; off <<= 1) {
            unsigned int n = __shfl_up_sync(0xFFFFFFFFu, iw, off);
            if (t >= off) iw += n;
        }
        ws[t] = iw - w;                     // exclusive warp base
        if (t == 31) g_bsum[sb] = iw;       // superblock total
    }
    __syncthreads();
    g_off[sb * K3A_TPB + t] = ws[warp] + (incl - v);
}

// K3b: one block (1024 threads) scans the 800 superblock sums (proven shape).
__global__ void __launch_bounds__(1024) k3b_base() {
    int t = threadIdx.x;
    int lane = t & 31;
    int warp = t >> 5;                      // 32 warps
    unsigned int v = (t < K3A_BLKS) ? g_bsum[t] : 0u;
    unsigned int incl = v;
    #pragma unroll
    for (int off = 1; off < 32; off <<= 1) {
        unsigned int n = __shfl_up_sync(0xFFFFFFFFu, incl, off);
        if (lane >= off) incl += n;
    }
    __shared__ unsigned int ws[32];
    if (lane == 31) ws[warp] = incl;
    __syncthreads();
    if (t < 32) {                           // warp 0 scans 32 warp sums
        unsigned int wv = ws[t];
        unsigned int iw = wv;
        #pragma unroll
        for (int off = 1; off < 32; off <<= 1) {
            unsigned int n = __shfl_up_sync(0xFFFFFFFFu, iw, off);
            if (t >= off) iw += n;
        }
        ws[t] = iw - wv;
    }
    __syncthreads();
    if (t < K3A_BLKS) g_bbase[t] = ws[warp] + (incl - v);
}

// ---------------------------------------------------------------------------
// K4: place each detection at its globally sorted position (proven).
__global__ void __launch_bounds__(CHUNK_PIX) k4_write(float* __restrict__ out, int nmax) {
    int blk = blockIdx.x;
    int t = threadIdx.x;
    int b     = blk / NCHUNK;
    int chunk = blk - b * NCHUNK;
    int hw = chunk * CHUNK_PIX + t;
    int p  = b * HWn + hw;
    float h = (float)(hw / Wn);
    float w = (float)(hw % Wn);
    float* kp = out + 2u * (unsigned)nmax;
    #pragma unroll
    for (int slot = 0; slot < 2; slot++) {
        unsigned int rec = g_rec[2*p + slot];
        if (rec != 0xFFFFFFFFu) {
            unsigned int c    = rec >> 16;
            unsigned int rank = rec & 0xFFFFu;
            unsigned int idx  = (unsigned)((b * Cn + (int)c) * NCHUNK + chunk);
            unsigned int n = g_bbase[idx >> 10] + g_off[idx] + rank;
            if (n < (unsigned)nmax) {
                out[2u*n + 0u] = h;
                out[2u*n + 1u] = w;
                kp [2u*n + 0u] = 8.0f * h + 3.5f;   // ((p*2+.5)*2+.5)*2+.5
                kp [2u*n + 1u] = 8.0f * w + 3.5f;
            }
        }
    }
}

// ---------------------------------------------------------------------------
extern "C" void kernel_launch(void* const* d_in, const int* in_sizes, int n_in,
                              void* d_out, int out_size) {
    const float* x = (const float*)d_in[0];
    float* out = (float*)d_out;
    int nmax = out_size / 4;

    {   // K0: output padding (float4)
        int n4 = out_size / 4;
        int half4 = (out_size / 2) / 4;
        k0_init<<<(n4 + 255) / 256, 256>>>((float4*)out, n4, half4);
    }
    kfused<<<NBLK, TPB_F>>>(x);          // ONE 210MB pass, 16 threads/pixel
    k3a_scan<<<K3A_BLKS, K3A_TPB>>>();   // scan 819200 (b,c,chunk) counts
    k3b_base<<<1, 1024>>>();             // 800 superblock bases
    k4_write<<<NBLK, CHUNK_PIX>>>(out, nmax);
}

// round 13
// speedup vs baseline: 1.8508x; 1.8508x over previous
#include <cuda_runtime.h>

// Problem constants
#define Bn 16
#define Cn 512
#define Hn 80
#define Wn 80
#define HWn (Hn*Wn)          // 6400
#define CHWn (Cn*HWn)        // 3276800
#define NPIX (Bn*HWn)        // 102400

// counting-sort chunks: 128 pixels per block, 8 channel-groups (R11-proven optimum)
#define CHUNK_PIX 128
#define NGRP 8
#define GRP_C (Cn/NGRP)                 // 64 channels per group
#define TPB_F (CHUNK_PIX*NGRP)          // 1024
#define NCHUNK 50                       // chunks per batch (6400/128)
#define NBLK (Bn*NCHUNK)                // 800 blocks
#define NCNT (Bn*Cn*NCHUNK)             // 409600 counters, order (b,c,chunk)

// two-level scan of NCNT counters: 400 blocks x 1024 (exact)
#define K3A_BLKS 400
#define K3A_TPB 1024

// ---- scratch (allocation-free: __device__ globals) ----
__device__ unsigned int g_rec[NPIX * 2];   // 2 det slots/pixel: (c<<16)|rank, ~0u=empty
__device__ unsigned int g_cnt[NCNT];       // counts per (b,c,chunk)
__device__ unsigned int g_off[NCNT];       // exclusive within 1024-superblock
__device__ unsigned int g_bsum[K3A_BLKS];
__device__ unsigned int g_bbase[K3A_BLKS];
__device__ unsigned int g_done;            // last-block ticket (reset by kfused)

// ---------------------------------------------------------------------------
// neighbor test: v (>=0) must be >= all in-bounds raw 3x3 neighbors
// (v >= relu(n) <=> v >= n when v >= 0). Rare path.
__device__ __noinline__ bool neigh_ok(const float* __restrict__ plane,
                                      float v, int h, int w) {
    #pragma unroll
    for (int dh = -1; dh <= 1; dh++) {
        int nh = h + dh;
        if (nh < 0 || nh >= Hn) continue;
        #pragma unroll
        for (int dw = -1; dw <= 1; dw++) {
            if (dh == 0 && dw == 0) continue;
            int nw = w + dw;
            if (nw < 0 || nw >= Wn) continue;
            if (v < plane[nh * Wn + nw]) return false;
        }
    }
    return true;
}

// ---------------------------------------------------------------------------
// Fused: 8 threads per pixel (64 channels each), 128 pixels per block.
// R11-proven body + folded-in output-padding init + g_done reset.
__global__ void __launch_bounds__(TPB_F) kfused(const float* __restrict__ x,
                                                float4* __restrict__ out4,
                                                int n4, int half4) {
    __shared__ unsigned int s_mb[TPB_F];     // group max bits (relu >= 0)
    __shared__ unsigned int s_cand[TPB_F];   // cA | cB<<16 (0xFFFF = empty)
    __shared__ unsigned char s_nd[TPB_F];    // tie count (saturated at 3)
    __shared__ unsigned int bucket[Cn];      // per-channel counts, this chunk
    __shared__ unsigned int ch[CHUNK_PIX];   // packed det channels per pixel

    int blk = blockIdx.x;                    // 800
    int t = threadIdx.x;

    // folded K0: output padding (each block covers its slice, coalesced)
    if (t < CHUNK_PIX) {
        for (int i4 = blk * CHUNK_PIX + t; i4 < n4; i4 += NBLK * CHUNK_PIX) {
            out4[i4] = (i4 < half4) ? make_float4(-1.f, -1.f, -1.f, -1.f)
                                    : make_float4(-4.5f, -4.5f, -4.5f, -4.5f);
        }
    }
    if (blk == 0 && t == 0) g_done = 0u;     // reset last-block ticket each replay

    int pix = t & (CHUNK_PIX - 1);
    int grp = t >> 7;                        // 0..7
    int b     = blk / NCHUNK;
    int chunk = blk - b * NCHUNK;
    int hw = chunk * CHUNK_PIX + pix;
    int cbase = grp * GRP_C;
    const float* base = x + (size_t)b * CHWn + (size_t)cbase * HWn + hw;

    if (t < Cn) bucket[t] = 0u;

    // ---- Phase A: tie-tracking scan of 64 channels (4 accumulators) ----
    float m0 = 0.f, m1 = 0.f, m2 = 0.f, m3 = 0.f;
    int   a0 = -1,  a1 = -1,  a2 = -1,  a3 = -1;     // first tied channel
    int   b0 = -1,  b1 = -1,  b2 = -1,  b3 = -1;     // second tied channel
    int   n0 = 0,   n1 = 0,   n2 = 0,   n3 = 0;      // tie counts
    #pragma unroll 8
    for (int c = 0; c < GRP_C; c += 4) {
        float v0 = fmaxf(base[(size_t)(c+0) * HWn], 0.f);
        float v1 = fmaxf(base[(size_t)(c+1) * HWn], 0.f);
        float v2 = fmaxf(base[(size_t)(c+2) * HWn], 0.f);
        float v3 = fmaxf(base[(size_t)(c+3) * HWn], 0.f);
        if (v0 > m0)      { m0 = v0; a0 = cbase + c+0; n0 = 1; }
        else if (v0 == m0 && m0 > 0.f) { if (n0 == 1) b0 = cbase + c+0; n0++; }
        if (v1 > m1)      { m1 = v1; a1 = cbase + c+1; n1 = 1; }
        else if (v1 == m1 && m1 > 0.f) { if (n1 == 1) b1 = cbase + c+1; n1++; }
        if (v2 > m2)      { m2 = v2; a2 = cbase + c+2; n2 = 1; }
        else if (v2 == m2 && m2 > 0.f) { if (n2 == 1) b2 = cbase + c+2; n2++; }
        if (v3 > m3)      { m3 = v3; a3 = cbase + c+3; n3 = 1; }
        else if (v3 == m3 && m3 > 0.f) { if (n3 == 1) b3 = cbase + c+3; n3++; }
    }
    float m = fmaxf(fmaxf(m0, m1), fmaxf(m2, m3));

    // per-thread merge: two smallest tied channels within this group (proven)
    int cand[8];
    #pragma unroll
    for (int i = 0; i < 8; i++) cand[i] = 0x7FFFFFFF;
    int ndT = 0;
    if (m > 0.f) {
        if (m0 == m) { cand[0] = a0; if (n0 > 1) cand[1] = b0; ndT += n0; }
        if (m1 == m) { cand[2] = a1; if (n1 > 1) cand[3] = b1; ndT += n1; }
        if (m2 == m) { cand[4] = a2; if (n2 > 1) cand[5] = b2; ndT += n2; }
        if (m3 == m) { cand[6] = a3; if (n3 > 1) cand[7] = b3; ndT += n3; }
    }
    int cA = 0x7FFFFFFF, cB = 0x7FFFFFFF;
    #pragma unroll
    for (int i = 0; i < 8; i++) cA = min(cA, cand[i]);
    #pragma unroll
    for (int i = 0; i < 8; i++) if (cand[i] > cA) cB = min(cB, cand[i]);

    s_mb[t]   = __float_as_uint(m);
    s_cand[t] = (unsigned)(cA & 0xFFFF) | ((unsigned)(cB & 0xFFFF) << 16);
    s_nd[t]   = (unsigned char)min(ndT, 3);
    __syncthreads();

    // ---- leader merge + Phase B + Phase C front half ----
    unsigned int c0 = 0xFFFFu, c1 = 0xFFFFu;
    if (t < CHUNK_PIX) {
        unsigned int mb = 0u;
        #pragma unroll
        for (int g = 0; g < NGRP; g++) mb = max(mb, s_mb[g * CHUNK_PIX + t]);
        unsigned int tA = 0xFFFFu, tB = 0xFFFFu;
        int ndtot = 0;
        if (mb != 0u) {                         // relu bits: 0 iff m == 0
            #pragma unroll
            for (int g = 0; g < NGRP; g++) {
                int gi = g * CHUNK_PIX + t;
                if (s_mb[gi] == mb) {
                    unsigned int pk = s_cand[gi];
                    unsigned int la = pk & 0xFFFFu, lb = pk >> 16;
                    if (la != 0xFFFFu) { if (tA == 0xFFFFu) tA = la; else if (tB == 0xFFFFu) tB = la; }
                    if (lb != 0xFFFFu) { if (tA == 0xFFFFu) tA = lb; else if (tB == 0xFFFFu) tB = lb; }
                    ndtot += (int)s_nd[gi];
                }
            }
        }
        float mv = __uint_as_float(mb);
        int h = hw / Wn, w = hw - (hw / Wn) * Wn;
        if (ndtot >= 1) {
            bool d0 = neigh_ok(x + (size_t)b * CHWn + (size_t)tA * HWn, mv, h, w);
            bool d1 = (ndtot >= 2) && (tB != 0xFFFFu) &&
                      neigh_ok(x + (size_t)b * CHWn + (size_t)tB * HWn, mv, h, w);
            if (d0) { c0 = tA; if (d1) c1 = tB; }
            else if (d1) { c0 = tB; }
        } else if (mb == 0u) {
            // degenerate pixel (all channels <= 0): prob 2^-512; exact rescan.
            int nd = 0;
            for (int c = 0; c < Cn && nd < 2; c++) {
                const float* plane = x + (size_t)b * CHWn + (size_t)c * HWn;
                if (fmaxf(plane[h * Wn + w], 0.f) == 0.f && neigh_ok(plane, 0.f, h, w)) {
                    if (nd == 0) c0 = (unsigned)c; else c1 = (unsigned)c;
                    nd++;
                }
            }
        }
        if (c0 != 0xFFFFu) atomicAdd(&bucket[c0], 1u);
        if (c1 != 0xFFFFu) atomicAdd(&bucket[c1], 1u);
        ch[t] = c0 | (c1 << 16);
    }
    __syncthreads();

    // ---- Phase C back half: exact pixel-order ranks (proven) ----
    if (t < CHUNK_PIX) {
        unsigned int r0 = 0, r1 = 0;
        if (c0 != 0xFFFFu) {
            for (int q = 0; q < t; q++) {
                unsigned int wv = ch[q];
                unsigned int lo = wv & 0xFFFFu, hi = wv >> 16;
                r0 += (lo == c0) + (hi == c0);
                r1 += (lo == c1) + (hi == c1);
            }
        }
        int p = b * HWn + hw;
        g_rec[2*p + 0] = (c0 != 0xFFFFu) ? ((c0 << 16) | r0) : 0xFFFFFFFFu;
        g_rec[2*p + 1] = (c1 != 0xFFFFu) ? ((c1 << 16) | r1) : 0xFFFFFFFFu;
    }
    if (t < Cn)
        g_cnt[(b * Cn + t) * NCHUNK + chunk] = bucket[t];
}

// ---------------------------------------------------------------------------
// K3a: 400 blocks x 1024 counts: local exclusive scan + block sum (proven body),
// then the LAST block to finish runs the k3b base scan in-place.
__global__ void __launch_bounds__(K3A_TPB) k3a_scan() {
    int sb = blockIdx.x;
    int t = threadIdx.x;
    int lane = t & 31;
    int warp = t >> 5;
    unsigned int v = g_cnt[sb * K3A_TPB + t];
    unsigned int incl = v;
    #pragma unroll
    for (int off = 1; off < 32; off <<= 1) {
        unsigned int n = __shfl_up_sync(0xFFFFFFFFu, incl, off);
        if (lane >= off) incl += n;
    }
    __shared__ unsigned int ws[32];
    if (lane == 31) ws[warp] = incl;
    __syncthreads();
    if (t < 32) {
        unsigned int w = ws[t];
        unsigned int iw = w;
        #pragma unroll
        for (int off = 1; off < 32; off <<= 1) {
            unsigned int n = __shfl_up_sync(0xFFFFFFFFu, iw, off);
            if (t >= off) iw += n;
        }
        ws[t] = iw - w;                     // exclusive warp base
        if (t == 31) g_bsum[sb] = iw;       // superblock total
    }
    __syncthreads();
    g_off[sb * K3A_TPB + t] = ws[warp] + (incl - v);

    // ---- last-block merge of the k3b base scan ----
    __threadfence();                        // make g_bsum/g_off globally visible
    __shared__ unsigned int s_last;
    if (t == 0) {
        unsigned int old = atomicAdd(&g_done, 1u);
        s_last = (old == K3A_BLKS - 1) ? 1u : 0u;
    }
    __syncthreads();
    if (s_last) {                           // proven k3b body (400 sums, 32 warps)
        unsigned int bv = (t < K3A_BLKS) ? g_bsum[t] : 0u;
        unsigned int bincl = bv;
        #pragma unroll
        for (int off = 1; off < 32; off <<= 1) {
            unsigned int n = __shfl_up_sync(0xFFFFFFFFu, bincl, off);
            if (lane >= off) bincl += n;
        }
        __shared__ unsigned int ws2[32];
        if (lane == 31) ws2[warp] = bincl;
        __syncthreads();
        if (t < 32) {
            unsigned int wv = ws2[t];
            unsigned int iw = wv;
            #pragma unroll
            for (int off = 1; off < 32; off <<= 1) {
                unsigned int n = __shfl_up_sync(0xFFFFFFFFu, iw, off);
                if (t >= off) iw += n;
            }
            ws2[t] = iw - wv;
        }
        __syncthreads();
        if (t < K3A_BLKS) g_bbase[t] = ws2[warp] + (bincl - bv);
    }
}

// ---------------------------------------------------------------------------
// K4: place each detection at its globally sorted position (proven).
__global__ void __launch_bounds__(CHUNK_PIX) k4_write(float* __restrict__ out, int nmax) {
    int blk = blockIdx.x;
    int t = threadIdx.x;
    int b     = blk / NCHUNK;
    int chunk = blk - b * NCHUNK;
    int hw = chunk * CHUNK_PIX + t;
    int p  = b * HWn + hw;
    float h = (float)(hw / Wn);
    float w = (float)(hw % Wn);
    float* kp = out + 2u * (unsigned)nmax;
    #pragma unroll
    for (int slot = 0; slot < 2; slot++) {
        unsigned int rec = g_rec[2*p + slot];
        if (rec != 0xFFFFFFFFu) {
            unsigned int c    = rec >> 16;
            unsigned int rank = rec & 0xFFFFu;
            unsigned int idx  = (unsigned)((b * Cn + (int)c) * NCHUNK + chunk);
            unsigned int n = g_bbase[idx >> 10] + g_off[idx] + rank;
            if (n < (unsigned)nmax) {
                out[2u*n + 0u] = h;
                out[2u*n + 1u] = w;
                kp [2u*n + 0u] = 8.0f * h + 3.5f;   // ((p*2+.5)*2+.5)*2+.5
                kp [2u*n + 1u] = 8.0f * w + 3.5f;
            }
        }
    }
}

// ---------------------------------------------------------------------------
extern "C" void kernel_launch(void* const* d_in, const int* in_sizes, int n_in,
                              void* d_out, int out_size) {
    const float* x = (const float*)d_in[0];
    float* out = (float*)d_out;
    int nmax = out_size / 4;
    int n4 = out_size / 4;          // float4 count
    int half4 = (out_size / 2) / 4;

    kfused<<<NBLK, TPB_F>>>(x, (float4*)out, n4, half4);  // pass + padding + reset
    k3a_scan<<<K3A_BLKS, K3A_TPB>>>();                    // scan + last-block bases
    k4_write<<<NBLK, CHUNK_PIX>>>(out, nmax);
}

// round 14
// speedup vs baseline: 2.0201x; 1.0914x over previous
#include <cuda_runtime.h>

// Problem constants
#define Bn 16
#define Cn 512
#define Hn 80
#define Wn 80
#define HWn (Hn*Wn)          // 6400
#define CHWn (Cn*HWn)        // 3276800
#define NPIX (Bn*HWn)        // 102400

// counting-sort chunks: 128 pixels per block (R11/R13-proven bookkeeping).
// NEW decomposition inside kfused: 16 channel-groups x 32 pixel-quads = 512 thr,
// each thread loads float4 (4 pixels) x 32 channels.
#define CHUNK_PIX 128
#define NGRP 16
#define GRP_C (Cn/NGRP)                 // 32 channels per group
#define QUADS (CHUNK_PIX/4)             // 32 quads per chunk
#define TPB_F (QUADS*NGRP)              // 512 threads
#define NCHUNK 50                       // chunks per batch (6400/128)
#define NBLK (Bn*NCHUNK)                // 800 blocks
#define NCNT (Bn*Cn*NCHUNK)             // 409600 counters, order (b,c,chunk)

// two-level scan of NCNT counters: 400 blocks x 1024 (R13-proven)
#define K3A_BLKS 400
#define K3A_TPB 1024

// ---- scratch (allocation-free: __device__ globals) ----
__device__ unsigned int g_rec[NPIX * 2];   // 2 det slots/pixel: (c<<16)|rank, ~0u=empty
__device__ unsigned int g_cnt[NCNT];       // counts per (b,c,chunk)
__device__ unsigned int g_off[NCNT];       // exclusive within 1024-superblock
__device__ unsigned int g_bsum[K3A_BLKS];
__device__ unsigned int g_bbase[K3A_BLKS];
__device__ unsigned int g_done;            // last-block ticket (reset by kfused)

// ---------------------------------------------------------------------------
// neighbor test: v (>=0) must be >= all in-bounds raw 3x3 neighbors
// (v >= relu(n) <=> v >= n when v >= 0). Rare path.
__device__ __noinline__ bool neigh_ok(const float* __restrict__ plane,
                                      float v, int h, int w) {
    #pragma unroll
    for (int dh = -1; dh <= 1; dh++) {
        int nh = h + dh;
        if (nh < 0 || nh >= Hn) continue;
        #pragma unroll
        for (int dw = -1; dw <= 1; dw++) {
            if (dh == 0 && dw == 0) continue;
            int nw = w + dw;
            if (nw < 0 || nw >= Wn) continue;
            if (v < plane[nh * Wn + nw]) return false;
        }
    }
    return true;
}

// ---------------------------------------------------------------------------
// Fused: per thread, 4 pixels (float4) x 32 channels. Sequential tie-tracking
// per pixel (the reference algorithm, per channel-group). Leader merge +
// Phase B + Phase C bodies are R13-proven verbatim (NGRP 8 -> 16 loop bound).
__global__ void __launch_bounds__(TPB_F, 2) kfused(const float* __restrict__ x,
                                                   float4* __restrict__ out4,
                                                   int n4, int half4) {
    __shared__ unsigned int s_mb[NGRP * CHUNK_PIX];    // group max bits
    __shared__ unsigned int s_cand[NGRP * CHUNK_PIX];  // cA | cB<<16 (0xFFFF empty)
    __shared__ unsigned char s_nd[NGRP * CHUNK_PIX];   // tie count (sat 3)
    __shared__ unsigned int bucket[Cn];                // per-channel counts
    __shared__ unsigned int ch[CHUNK_PIX];             // packed det channels

    int blk = blockIdx.x;                    // 800
    int t = threadIdx.x;                     // 512
    int quad = t & (QUADS - 1);              // 0..31
    int grp  = t >> 5;                       // 0..15
    int b     = blk / NCHUNK;
    int chunk = blk - b * NCHUNK;
    int hw0 = chunk * CHUNK_PIX + quad * 4;  // first pixel of this thread's quad
    int cbase = grp * GRP_C;
    const float* base = x + (size_t)b * CHWn + (size_t)cbase * HWn + hw0;

    // folded K0: output padding (R13-proven: leaders cover n4 exactly)
    if (t < CHUNK_PIX) {
        for (int i4 = blk * CHUNK_PIX + t; i4 < n4; i4 += NBLK * CHUNK_PIX) {
            out4[i4] = (i4 < half4) ? make_float4(-1.f, -1.f, -1.f, -1.f)
                                    : make_float4(-4.5f, -4.5f, -4.5f, -4.5f);
        }
    }
    if (blk == 0 && t == 0) g_done = 0u;     // reset last-block ticket each replay

    if (t < Cn) bucket[t] = 0u;              // TPB_F=512=Cn: one each

    // ---- Phase A: sequential tie-tracking over 32 channels, 4 pixels ----
    float m0 = 0.f, m1 = 0.f, m2 = 0.f, m3 = 0.f;
    int   a0 = -1,  a1 = -1,  a2 = -1,  a3 = -1;     // first tied channel
    int   b0 = -1,  b1 = -1,  b2 = -1,  b3 = -1;     // second tied channel
    int   n0 = 0,   n1 = 0,   n2 = 0,   n3 = 0;      // tie counts
    #pragma unroll 8
    for (int c = 0; c < GRP_C; c++) {
        float4 v = *reinterpret_cast<const float4*>(base + (size_t)c * HWn);
        v.x = fmaxf(v.x, 0.f); v.y = fmaxf(v.y, 0.f);
        v.z = fmaxf(v.z, 0.f); v.w = fmaxf(v.w, 0.f);
        int cc = cbase + c;
        if (v.x > m0)      { m0 = v.x; a0 = cc; n0 = 1; }
        else if (v.x == m0 && m0 > 0.f) { if (n0 == 1) b0 = cc; n0++; }
        if (v.y > m1)      { m1 = v.y; a1 = cc; n1 = 1; }
        else if (v.y == m1 && m1 > 0.f) { if (n1 == 1) b1 = cc; n1++; }
        if (v.z > m2)      { m2 = v.z; a2 = cc; n2 = 1; }
        else if (v.z == m2 && m2 > 0.f) { if (n2 == 1) b2 = cc; n2++; }
        if (v.w > m3)      { m3 = v.w; a3 = cc; n3 = 1; }
        else if (v.w == m3 && m3 > 0.f) { if (n3 == 1) b3 = cc; n3++; }
    }

    // publish per-(group,pixel) results; layout [grp][pixel] for conflict-free
    // leader reads. a<b ascending by construction (sequential scan).
    {
        int sb = grp * CHUNK_PIX + quad * 4;
        s_mb[sb + 0] = __float_as_uint(m0);
        s_mb[sb + 1] = __float_as_uint(m1);
        s_mb[sb + 2] = __float_as_uint(m2);
        s_mb[sb + 3] = __float_as_uint(m3);
        s_cand[sb + 0] = (unsigned)((n0 >= 1 ? a0 : 0xFFFF) & 0xFFFF) | (((unsigned)((n0 >= 2 ? b0 : 0xFFFF) & 0xFFFF)) << 16);
        s_cand[sb + 1] = (unsigned)((n1 >= 1 ? a1 : 0xFFFF) & 0xFFFF) | (((unsigned)((n1 >= 2 ? b1 : 0xFFFF) & 0xFFFF)) << 16);
        s_cand[sb + 2] = (unsigned)((n2 >= 1 ? a2 : 0xFFFF) & 0xFFFF) | (((unsigned)((n2 >= 2 ? b2 : 0xFFFF) & 0xFFFF)) << 16);
        s_cand[sb + 3] = (unsigned)((n3 >= 1 ? a3 : 0xFFFF) & 0xFFFF) | (((unsigned)((n3 >= 2 ? b3 : 0xFFFF) & 0xFFFF)) << 16);
        s_nd[sb + 0] = (unsigned char)min(n0, 3);
        s_nd[sb + 1] = (unsigned char)min(n1, 3);
        s_nd[sb + 2] = (unsigned char)min(n2, 3);
        s_nd[sb + 3] = (unsigned char)min(n3, 3);
    }
    __syncthreads();

    // ---- leader merge + Phase B + Phase C front half (R13-proven body) ----
    unsigned int c0 = 0xFFFFu, c1 = 0xFFFFu;
    int hw = chunk * CHUNK_PIX + t;          // leader's pixel
    if (t < CHUNK_PIX) {
        unsigned int mb = 0u;
        #pragma unroll
        for (int g = 0; g < NGRP; g++) mb = max(mb, s_mb[g * CHUNK_PIX + t]);
        unsigned int tA = 0xFFFFu, tB = 0xFFFFu;
        int ndtot = 0;
        if (mb != 0u) {                         // relu bits: 0 iff m == 0
            #pragma unroll
            for (int g = 0; g < NGRP; g++) {
                int gi = g * CHUNK_PIX + t;
                if (s_mb[gi] == mb) {
                    unsigned int pk = s_cand[gi];
                    unsigned int la = pk & 0xFFFFu, lb = pk >> 16;
                    if (la != 0xFFFFu) { if (tA == 0xFFFFu) tA = la; else if (tB == 0xFFFFu) tB = la; }
                    if (lb != 0xFFFFu) { if (tA == 0xFFFFu) tA = lb; else if (tB == 0xFFFFu) tB = lb; }
                    ndtot += (int)s_nd[gi];
                }
            }
        }
        float mv = __uint_as_float(mb);
        int h = hw / Wn, w = hw - (hw / Wn) * Wn;
        if (ndtot >= 1) {
            bool d0 = neigh_ok(x + (size_t)b * CHWn + (size_t)tA * HWn, mv, h, w);
            bool d1 = (ndtot >= 2) && (tB != 0xFFFFu) &&
                      neigh_ok(x + (size_t)b * CHWn + (size_t)tB * HWn, mv, h, w);
            if (d0) { c0 = tA; if (d1) c1 = tB; }
            else if (d1) { c0 = tB; }
        } else if (mb == 0u) {
            // degenerate pixel (all channels <= 0): prob 2^-512; exact rescan.
            int nd = 0;
            for (int c = 0; c < Cn && nd < 2; c++) {
                const float* plane = x + (size_t)b * CHWn + (size_t)c * HWn;
                if (fmaxf(plane[h * Wn + w], 0.f) == 0.f && neigh_ok(plane, 0.f, h, w)) {
                    if (nd == 0) c0 = (unsigned)c; else c1 = (unsigned)c;
                    nd++;
                }
            }
        }
        if (c0 != 0xFFFFu) atomicAdd(&bucket[c0], 1u);
        if (c1 != 0xFFFFu) atomicAdd(&bucket[c1], 1u);
        ch[t] = c0 | (c1 << 16);
    }
    __syncthreads();

    // ---- Phase C back half: exact pixel-order ranks (proven) ----
    if (t < CHUNK_PIX) {
        unsigned int r0 = 0, r1 = 0;
        if (c0 != 0xFFFFu) {
            for (int q = 0; q < t; q++) {
                unsigned int wv = ch[q];
                unsigned int lo = wv & 0xFFFFu, hi = wv >> 16;
                r0 += (lo == c0) + (hi == c0);
                r1 += (lo == c1) + (hi == c1);
            }
        }
        int p = b * HWn + hw;
        g_rec[2*p + 0] = (c0 != 0xFFFFu) ? ((c0 << 16) | r0) : 0xFFFFFFFFu;
        g_rec[2*p + 1] = (c1 != 0xFFFFu) ? ((c1 << 16) | r1) : 0xFFFFFFFFu;
    }
    if (t < Cn)
        g_cnt[(b * Cn + t) * NCHUNK + chunk] = bucket[t];
}

// ---------------------------------------------------------------------------
// K3a: 400 blocks x 1024 counts + last-block k3b base scan (R13-proven).
__global__ void __launch_bounds__(K3A_TPB) k3a_scan() {
    int sb = blockIdx.x;
    int t = threadIdx.x;
    int lane = t & 31;
    int warp = t >> 5;
    unsigned int v = g_cnt[sb * K3A_TPB + t];
    unsigned int incl = v;
    #pragma unroll
    for (int off = 1; off < 32; off <<= 1) {
        unsigned int n = __shfl_up_sync(0xFFFFFFFFu, incl, off);
        if (lane >= off) incl += n;
    }
    __shared__ unsigned int ws[32];
    if (lane == 31) ws[warp] = incl;
    __syncthreads();
    if (t < 32) {
        unsigned int w = ws[t];
        unsigned int iw = w;
        #pragma unroll
        for (int off = 1; off < 32; off <<= 1) {
            unsigned int n = __shfl_up_sync(0xFFFFFFFFu, iw, off);
            if (t >= off) iw += n;
        }
        ws[t] = iw - w;                     // exclusive warp base
        if (t == 31) g_bsum[sb] = iw;       // superblock total
    }
    __syncthreads();
    g_off[sb * K3A_TPB + t] = ws[warp] + (incl - v);

    // ---- last-block merge of the k3b base scan ----
    __threadfence();
    __shared__ unsigned int s_last;
    if (t == 0) {
        unsigned int old = atomicAdd(&g_done, 1u);
        s_last = (old == K3A_BLKS - 1) ? 1u : 0u;
    }
    __syncthreads();
    if (s_last) {
        unsigned int bv = (t < K3A_BLKS) ? g_bsum[t] : 0u;
        unsigned int bincl = bv;
        #pragma unroll
        for (int off = 1; off < 32; off <<= 1) {
            unsigned int n = __shfl_up_sync(0xFFFFFFFFu, bincl, off);
            if (lane >= off) bincl += n;
        }
        __shared__ unsigned int ws2[32];
        if (lane == 31) ws2[warp] = bincl;
        __syncthreads();
        if (t < 32) {
            unsigned int wv = ws2[t];
            unsigned int iw = wv;
            #pragma unroll
            for (int off = 1; off < 32; off <<= 1) {
                unsigned int n = __shfl_up_sync(0xFFFFFFFFu, iw, off);
                if (t >= off) iw += n;
            }
            ws2[t] = iw - wv;
        }
        __syncthreads();
        if (t < K3A_BLKS) g_bbase[t] = ws2[warp] + (bincl - bv);
    }
}

// ---------------------------------------------------------------------------
// K4: place each detection at its globally sorted position (proven).
__global__ void __launch_bounds__(CHUNK_PIX) k4_write(float* __restrict__ out, int nmax) {
    int blk = blockIdx.x;
    int t = threadIdx.x;
    int b     = blk / NCHUNK;
    int chunk = blk - b * NCHUNK;
    int hw = chunk * CHUNK_PIX + t;
    int p  = b * HWn + hw;
    float h = (float)(hw / Wn);
    float w = (float)(hw % Wn);
    float* kp = out + 2u * (unsigned)nmax;
    #pragma unroll
    for (int slot = 0; slot < 2; slot++) {
        unsigned int rec = g_rec[2*p + slot];
        if (rec != 0xFFFFFFFFu) {
            unsigned int c    = rec >> 16;
            unsigned int rank = rec & 0xFFFFu;
            unsigned int idx  = (unsigned)((b * Cn + (int)c) * NCHUNK + chunk);
            unsigned int n = g_bbase[idx >> 10] + g_off[idx] + rank;
            if (n < (unsigned)nmax) {
                out[2u*n + 0u] = h;
                out[2u*n + 1u] = w;
                kp [2u*n + 0u] = 8.0f * h + 3.5f;   // ((p*2+.5)*2+.5)*2+.5
                kp [2u*n + 1u] = 8.0f * w + 3.5f;
            }
        }
    }
}

// ---------------------------------------------------------------------------
extern "C" void kernel_launch(void* const* d_in, const int* in_sizes, int n_in,
                              void* d_out, int out_size) {
    const float* x = (const float*)d_in[0];
    float* out = (float*)d_out;
    int nmax = out_size / 4;
    int n4 = out_size / 4;          // float4 count
    int half4 = (out_size / 2) / 4;

    kfused<<<NBLK, TPB_F>>>(x, (float4*)out, n4, half4);  // float4 pass + padding
    k3a_scan<<<K3A_BLKS, K3A_TPB>>>();                    // scan + last-block bases
    k4_write<<<NBLK, CHUNK_PIX>>>(out, nmax);
}

// round 15
// speedup vs baseline: 2.1953x; 1.0868x over previous
#include <cuda_runtime.h>

// Problem constants
#define Bn 16
#define Cn 512
#define Hn 80
#define Wn 80
#define HWn (Hn*Wn)          // 6400
#define CHWn (Cn*HWn)        // 3276800
#define NPIX (Bn*HWn)        // 102400

// counting-sort chunks: 128 pixels per block (R13/R14-proven bookkeeping).
// kfused decomposition: 16 channel-groups x 32 pixel-quads = 512 threads,
// each thread loads float4 (4 pixels) x 32 channels (one bit per channel).
#define CHUNK_PIX 128
#define NGRP 16
#define GRP_C (Cn/NGRP)                 // 32 channels per group = 1 mask word
#define QUADS (CHUNK_PIX/4)             // 32 quads per chunk
#define TPB_F (QUADS*NGRP)              // 512 threads
#define NCHUNK 50                       // chunks per batch (6400/128)
#define NBLK (Bn*NCHUNK)                // 800 blocks
#define NCNT (Bn*Cn*NCHUNK)             // 409600 counters, order (b,c,chunk)

// two-level scan of NCNT counters: 400 blocks x 1024 (R13-proven)
#define K3A_BLKS 400
#define K3A_TPB 1024

// ---- scratch (allocation-free: __device__ globals) ----
__device__ unsigned int g_rec[NPIX * 2];   // 2 det slots/pixel: (c<<16)|rank, ~0u=empty
__device__ unsigned int g_cnt[NCNT];       // counts per (b,c,chunk)
__device__ unsigned int g_off[NCNT];       // exclusive within 1024-superblock
__device__ unsigned int g_bsum[K3A_BLKS];
__device__ unsigned int g_bbase[K3A_BLKS];
__device__ unsigned int g_done;            // last-block ticket (reset by kfused)

// ---------------------------------------------------------------------------
// neighbor test: v (>=0) must be >= all in-bounds raw 3x3 neighbors
// (v >= relu(n) <=> v >= n when v >= 0). Rare path.
__device__ __noinline__ bool neigh_ok(const float* __restrict__ plane,
                                      float v, int h, int w) {
    #pragma unroll
    for (int dh = -1; dh <= 1; dh++) {
        int nh = h + dh;
        if (nh < 0 || nh >= Hn) continue;
        #pragma unroll
        for (int dw = -1; dw <= 1; dw++) {
            if (dh == 0 && dw == 0) continue;
            int nw = w + dw;
            if (nw < 0 || nw >= Wn) continue;
            if (v < plane[nh * Wn + nw]) return false;
        }
    }
    return true;
}

// ---------------------------------------------------------------------------
// Fused: per thread, 4 pixels (float4) x 32 channels. Running-max + tie
// BITMASK per pixel (exact for any tie count). Leader merge extracts the two
// smallest tied channels across groups; Phase B/C bodies R13/R14-proven.
__global__ void __launch_bounds__(TPB_F, 3) kfused(const float* __restrict__ x,
                                                   float4* __restrict__ out4,
                                                   int n4, int half4) {
    __shared__ unsigned int s_mb[NGRP * CHUNK_PIX];    // group max bits
    __shared__ unsigned int s_mask[NGRP * CHUNK_PIX];  // channels tying group max
    __shared__ unsigned int bucket[Cn];                // per-channel counts
    __shared__ unsigned int ch[CHUNK_PIX];             // packed det channels

    int blk = blockIdx.x;                    // 800
    int t = threadIdx.x;                     // 512
    int quad = t & (QUADS - 1);              // 0..31
    int grp  = t >> 5;                       // 0..15
    int b     = blk / NCHUNK;
    int chunk = blk - b * NCHUNK;
    int hw0 = chunk * CHUNK_PIX + quad * 4;  // first pixel of this thread's quad
    int cbase = grp * GRP_C;
    const float* base = x + (size_t)b * CHWn + (size_t)cbase * HWn + hw0;

    // folded K0: output padding (proven: leaders cover n4 exactly)
    if (t < CHUNK_PIX) {
        for (int i4 = blk * CHUNK_PIX + t; i4 < n4; i4 += NBLK * CHUNK_PIX) {
            out4[i4] = (i4 < half4) ? make_float4(-1.f, -1.f, -1.f, -1.f)
                                    : make_float4(-4.5f, -4.5f, -4.5f, -4.5f);
        }
    }
    if (blk == 0 && t == 0) g_done = 0u;     // reset last-block ticket each replay

    if (t < Cn) bucket[t] = 0u;              // TPB_F=512=Cn: one each

    // ---- Phase A: running max + tie bitmask over 32 channels, 4 pixels ----
    float m0 = 0.f, m1 = 0.f, m2 = 0.f, m3 = 0.f;
    unsigned int k0 = 0u, k1 = 0u, k2 = 0u, k3 = 0u;
    #pragma unroll 8
    for (int c = 0; c < GRP_C; c++) {
        float4 v = *reinterpret_cast<const float4*>(base + (size_t)c * HWn);
        v.x = fmaxf(v.x, 0.f); v.y = fmaxf(v.y, 0.f);
        v.z = fmaxf(v.z, 0.f); v.w = fmaxf(v.w, 0.f);
        unsigned int bit = 1u << c;
        if (v.x > m0)       { m0 = v.x; k0 = bit; }
        else if (v.x == m0) { k0 |= bit; }
        if (v.y > m1)       { m1 = v.y; k1 = bit; }
        else if (v.y == m1) { k1 |= bit; }
        if (v.z > m2)       { m2 = v.z; k2 = bit; }
        else if (v.z == m2) { k2 |= bit; }
        if (v.w > m3)       { m3 = v.w; k3 = bit; }
        else if (v.w == m3) { k3 |= bit; }
    }
    // (mask bits accumulated while m==0 are only consulted if the FINAL pixel
    //  max is 0, which routes to the degenerate rescan path instead.)

    // publish per-(group,pixel) results; layout [grp][pixel]
    {
        int sb = grp * CHUNK_PIX + quad * 4;
        s_mb[sb + 0] = __float_as_uint(m0);  s_mask[sb + 0] = k0;
        s_mb[sb + 1] = __float_as_uint(m1);  s_mask[sb + 1] = k1;
        s_mb[sb + 2] = __float_as_uint(m2);  s_mask[sb + 2] = k2;
        s_mb[sb + 3] = __float_as_uint(m3);  s_mask[sb + 3] = k3;
    }
    __syncthreads();

    // ---- leader merge + Phase B + Phase C front half ----
    unsigned int c0 = 0xFFFFu, c1 = 0xFFFFu;
    int hw = chunk * CHUNK_PIX + t;          // leader's pixel
    if (t < CHUNK_PIX) {
        unsigned int mb = 0u;
        #pragma unroll
        for (int g = 0; g < NGRP; g++) mb = max(mb, s_mb[g * CHUNK_PIX + t]);
        unsigned int tA = 0xFFFFu, tB = 0xFFFFu;
        int ndtot = 0;
        if (mb != 0u) {                         // relu bits: 0 iff m == 0
            #pragma unroll
            for (int g = 0; g < NGRP; g++) {
                int gi = g * CHUNK_PIX + t;
                if (s_mb[gi] == mb) {
                    unsigned int mk = s_mask[gi];
                    ndtot += __popc(mk);
                    while (mk && tB == 0xFFFFu) {   // ascending channel order
                        int bit = __ffs(mk) - 1;
                        mk &= mk - 1;
                        unsigned int cc = (unsigned)(g * GRP_C + bit);
                        if (tA == 0xFFFFu) tA = cc; else tB = cc;
                    }
                }
            }
        }
        float mv = __uint_as_float(mb);
        int h = hw / Wn, w = hw - (hw / Wn) * Wn;
        if (ndtot >= 1) {
            bool d0 = neigh_ok(x + (size_t)b * CHWn + (size_t)tA * HWn, mv, h, w);
            bool d1 = (ndtot >= 2) && (tB != 0xFFFFu) &&
                      neigh_ok(x + (size_t)b * CHWn + (size_t)tB * HWn, mv, h, w);
            if (d0) { c0 = tA; if (d1) c1 = tB; }
            else if (d1) { c0 = tB; }
        } else if (mb == 0u) {
            // degenerate pixel (all channels <= 0): prob 2^-512; exact rescan.
            int nd = 0;
            for (int c = 0; c < Cn && nd < 2; c++) {
                const float* plane = x + (size_t)b * CHWn + (size_t)c * HWn;
                if (fmaxf(plane[h * Wn + w], 0.f) == 0.f && neigh_ok(plane, 0.f, h, w)) {
                    if (nd == 0) c0 = (unsigned)c; else c1 = (unsigned)c;
                    nd++;
                }
            }
        }
        if (c0 != 0xFFFFu) atomicAdd(&bucket[c0], 1u);
        if (c1 != 0xFFFFu) atomicAdd(&bucket[c1], 1u);
        ch[t] = c0 | (c1 << 16);
    }
    __syncthreads();

    // ---- Phase C back half: exact pixel-order ranks (proven) ----
    if (t < CHUNK_PIX) {
        unsigned int r0 = 0, r1 = 0;
        if (c0 != 0xFFFFu) {
            for (int q = 0; q < t; q++) {
                unsigned int wv = ch[q];
                unsigned int lo = wv & 0xFFFFu, hi = wv >> 16;
                r0 += (lo == c0) + (hi == c0);
                r1 += (lo == c1) + (hi == c1);
            }
        }
        int p = b * HWn + hw;
        g_rec[2*p + 0] = (c0 != 0xFFFFu) ? ((c0 << 16) | r0) : 0xFFFFFFFFu;
        g_rec[2*p + 1] = (c1 != 0xFFFFu) ? ((c1 << 16) | r1) : 0xFFFFFFFFu;
    }
    if (t < Cn)
        g_cnt[(b * Cn + t) * NCHUNK + chunk] = bucket[t];
}

// ---------------------------------------------------------------------------
// K3a: 400 blocks x 1024 counts + last-block k3b base scan (R13-proven).
__global__ void __launch_bounds__(K3A_TPB) k3a_scan() {
    int sb = blockIdx.x;
    int t = threadIdx.x;
    int lane = t & 31;
    int warp = t >> 5;
    unsigned int v = g_cnt[sb * K3A_TPB + t];
    unsigned int incl = v;
    #pragma unroll
    for (int off = 1; off < 32; off <<= 1) {
        unsigned int n = __shfl_up_sync(0xFFFFFFFFu, incl, off);
        if (lane >= off) incl += n;
    }
    __shared__ unsigned int ws[32];
    if (lane == 31) ws[warp] = incl;
    __syncthreads();
    if (t < 32) {
        unsigned int w = ws[t];
        unsigned int iw = w;
        #pragma unroll
        for (int off = 1; off < 32; off <<= 1) {
            unsigned int n = __shfl_up_sync(0xFFFFFFFFu, iw, off);
            if (t >= off) iw += n;
        }
        ws[t] = iw - w;                     // exclusive warp base
        if (t == 31) g_bsum[sb] = iw;       // superblock total
    }
    __syncthreads();
    g_off[sb * K3A_TPB + t] = ws[warp] + (incl - v);

    // ---- last-block merge of the k3b base scan ----
    __threadfence();
    __shared__ unsigned int s_last;
    if (t == 0) {
        unsigned int old = atomicAdd(&g_done, 1u);
        s_last = (old == K3A_BLKS - 1) ? 1u : 0u;
    }
    __syncthreads();
    if (s_last) {
        unsigned int bv = (t < K3A_BLKS) ? g_bsum[t] : 0u;
        unsigned int bincl = bv;
        #pragma unroll
        for (int off = 1; off < 32; off <<= 1) {
            unsigned int n = __shfl_up_sync(0xFFFFFFFFu, bincl, off);
            if (lane >= off) bincl += n;
        }
        __shared__ unsigned int ws2[32];
        if (lane == 31) ws2[warp] = bincl;
        __syncthreads();
        if (t < 32) {
            unsigned int wv = ws2[t];
            unsigned int iw = wv;
            #pragma unroll
            for (int off = 1; off < 32; off <<= 1) {
                unsigned int n = __shfl_up_sync(0xFFFFFFFFu, iw, off);
                if (t >= off) iw += n;
            }
            ws2[t] = iw - wv;
        }
        __syncthreads();
        if (t < K3A_BLKS) g_bbase[t] = ws2[warp] + (bincl - bv);
    }
}

// ---------------------------------------------------------------------------
// K4: place each detection at its globally sorted position (proven).
__global__ void __launch_bounds__(CHUNK_PIX) k4_write(float* __restrict__ out, int nmax) {
    int blk = blockIdx.x;
    int t = threadIdx.x;
    int b     = blk / NCHUNK;
    int chunk = blk - b * NCHUNK;
    int hw = chunk * CHUNK_PIX + t;
    int p  = b * HWn + hw;
    float h = (float)(hw / Wn);
    float w = (float)(hw % Wn);
    float* kp = out + 2u * (unsigned)nmax;
    #pragma unroll
    for (int slot = 0; slot < 2; slot++) {
        unsigned int rec = g_rec[2*p + slot];
        if (rec != 0xFFFFFFFFu) {
            unsigned int c    = rec >> 16;
            unsigned int rank = rec & 0xFFFFu;
            unsigned int idx  = (unsigned)((b * Cn + (int)c) * NCHUNK + chunk);
            unsigned int n = g_bbase[idx >> 10] + g_off[idx] + rank;
            if (n < (unsigned)nmax) {
                out[2u*n + 0u] = h;
                out[2u*n + 1u] = w;
                kp [2u*n + 0u] = 8.0f * h + 3.5f;   // ((p*2+.5)*2+.5)*2+.5
                kp [2u*n + 1u] = 8.0f * w + 3.5f;
            }
        }
    }
}

// ---------------------------------------------------------------------------
extern "C" void kernel_launch(void* const* d_in, const int* in_sizes, int n_in,
                              void* d_out, int out_size) {
    const float* x = (const float*)d_in[0];
    float* out = (float*)d_out;
    int nmax = out_size / 4;
    int n4 = out_size / 4;          // float4 count
    int half4 = (out_size / 2) / 4;

    kfused<<<NBLK, TPB_F>>>(x, (float4*)out, n4, half4);  // float4 pass + bitmask ties
    k3a_scan<<<K3A_BLKS, K3A_TPB>>>();                    // scan + last-block bases
    k4_write<<<NBLK, CHUNK_PIX>>>(out, nmax);
}